// round 8
// baseline (speedup 1.0000x reference)
#include <cuda_runtime.h>
#include <cuda_fp16.h>
#include <math.h>
#include <stdint.h>

#define T_   64
#define B_   512
#define D_   768
#define H_   12
#define HD_  64
#define E3_  2304
#define NROWS (T_*B_)

// scratch
__device__ __align__(256) float g_out[(size_t)NROWS * D_];
__device__ __align__(256) float g_mean[T_ * D_];
__device__ __align__(256) __half g_qkv[(size_t)NROWS * E3_];
__device__ __align__(256) __half g_node[(size_t)NROWS * D_];
__device__ __align__(256) __half g_ctx [(size_t)NROWS * D_];
__device__ __align__(256) __half g_w1[(size_t)E3_ * D_];
__device__ __align__(256) __half g_w2[(size_t)D_ * D_];

__device__ __forceinline__ uint32_t smem_u32(const void* p) {
    uint32_t a;
    asm("{ .reg .u64 t; cvta.to.shared.u64 t, %1; cvt.u32.u64 %0, t; }" : "=r"(a) : "l"(p));
    return a;
}
__device__ __forceinline__ void cp_async16(uint32_t s, const void* g) {
    asm volatile("cp.async.cg.shared.global [%0], [%1], 16;" :: "r"(s), "l"(g) : "memory");
}
__device__ __forceinline__ void cp_commit() { asm volatile("cp.async.commit_group;" ::: "memory"); }
__device__ __forceinline__ void cp_wait1()  { asm volatile("cp.async.wait_group 1;" ::: "memory"); }
__device__ __forceinline__ void cp_wait0()  { asm volatile("cp.async.wait_group 0;" ::: "memory"); }
__device__ __forceinline__ void ldsm4(uint32_t* r, uint32_t addr) {
    asm volatile("ldmatrix.sync.aligned.m8n8.x4.shared.b16 {%0,%1,%2,%3}, [%4];"
                 : "=r"(r[0]), "=r"(r[1]), "=r"(r[2]), "=r"(r[3]) : "r"(addr));
}
__device__ __forceinline__ void mma16816(float* d, const uint32_t* a, uint32_t b0, uint32_t b1) {
    asm volatile(
        "mma.sync.aligned.m16n8k16.row.col.f32.f16.f16.f32 "
        "{%0,%1,%2,%3}, {%4,%5,%6,%7}, {%8,%9}, {%0,%1,%2,%3};"
        : "+f"(d[0]), "+f"(d[1]), "+f"(d[2]), "+f"(d[3])
        : "r"(a[0]), "r"(a[1]), "r"(a[2]), "r"(a[3]), "r"(b0), "r"(b1));
}
__device__ __forceinline__ uint32_t pack_half2(float a, float b) {
    __half2 h = __floats2half2_rn(a, b);
    return *reinterpret_cast<uint32_t*>(&h);
}

// ---------------------------------------------------------------------------
// fp32 -> fp16 convert
// ---------------------------------------------------------------------------
__global__ __launch_bounds__(256) void cvt_kernel(
    const float4* __restrict__ x, __half2* __restrict__ hi, int n4)
{
    int i = blockIdx.x * 256 + threadIdx.x;
    if (i >= n4) return;
    float4 v = x[i];
    hi[2*i]   = __half2(__float2half_rn(v.x), __float2half_rn(v.y));
    hi[2*i+1] = __half2(__float2half_rn(v.z), __float2half_rn(v.w));
}

// ---------------------------------------------------------------------------
// mma.sync fp16 GEMM: C[m,n] = bias[n] + sum_k A[m,k]*W[n,k], K=768.
// Single pass. 128x128 CTA tile, BK=32, 2-stage cp.async, 8 warps (2m x 4n).
// smem: 2 stages x 2 tiles x 10240B = 40KB.
// do_split=1: write fp16 C (cols < scale_cols scaled by 0.125)
// ---------------------------------------------------------------------------
#define RS   80
#define TOFF 10240
#define SOFF 20480

__global__ __launch_bounds__(256, 2) void gemm_mma(
    const __half* __restrict__ Ahi, const __half* __restrict__ Bhi,
    const float* __restrict__ bias, float* __restrict__ C,
    __half* __restrict__ Chi,
    int N, int do_split, int scale_cols)
{
    extern __shared__ char smem[];
    const uint32_t sb = smem_u32(smem);
    const int tid = threadIdx.x;
    const int wid = tid >> 5, lane = tid & 31;
    const int wm = wid & 1, wn = wid >> 1;
    const int m0 = blockIdx.y * 128;
    const int n0 = blockIdx.x * 128;

    const __half* srcs[2] = {Ahi, Bhi};
    const int r0s[2] = {m0, n0};
    const int crow = tid >> 2;
    const int cc4  = tid & 3;

    float acc[4][4][4] = {};

    const int lrow  = ((lane >> 3) & 1) * 8 + (lane & 7);
    const int lkoff = (lane >> 4) * 16;
    const uint32_t a_base = sb + (uint32_t)(wm * 64 + lrow) * RS + lkoff;
    const uint32_t b_base = sb + (uint32_t)(wn * 32 + lrow) * RS + lkoff;

    {
        #pragma unroll
        for (int tI = 0; tI < 2; ++tI)
            #pragma unroll
            for (int it = 0; it < 2; ++it) {
                int row = crow + it * 64;
                cp_async16(sb + tI * TOFF + row * RS + cc4 * 16,
                           srcs[tI] + (size_t)(r0s[tI] + row) * D_ + cc4 * 8);
            }
        cp_commit();
    }

    for (int c = 0; c < 24; ++c) {
        if (c < 23) {
            const int k0 = (c + 1) * 32;
            const uint32_t base = sb + ((c + 1) & 1) * SOFF;
            #pragma unroll
            for (int tI = 0; tI < 2; ++tI)
                #pragma unroll
                for (int it = 0; it < 2; ++it) {
                    int row = crow + it * 64;
                    cp_async16(base + tI * TOFF + row * RS + cc4 * 16,
                               srcs[tI] + (size_t)(r0s[tI] + row) * D_ + k0 + cc4 * 8);
                }
            cp_commit();
            cp_wait1();
        } else {
            cp_wait0();
        }
        __syncthreads();

        const uint32_t st = ((uint32_t)(c & 1)) * SOFF;
        #pragma unroll
        for (int ks = 0; ks < 2; ++ks) {
            const uint32_t ko = ks * 32;
            uint32_t ah[4][4], bh[2][4];
            #pragma unroll
            for (int mi = 0; mi < 4; ++mi)
                ldsm4(ah[mi], a_base + st + 0 * TOFF + mi * 16 * RS + ko);
            #pragma unroll
            for (int nt = 0; nt < 2; ++nt)
                ldsm4(bh[nt], b_base + st + 1 * TOFF + nt * 16 * RS + ko);
            #pragma unroll
            for (int mi = 0; mi < 4; ++mi)
                #pragma unroll
                for (int ni = 0; ni < 4; ++ni) {
                    const int nt = ni >> 1, hl = ni & 1;
                    mma16816(acc[mi][ni], ah[mi], bh[nt][hl], bh[nt][hl + 2]);
                }
        }
        __syncthreads();
    }

    const int g   = lane >> 2;
    const int tig = lane & 3;
    #pragma unroll
    for (int mi = 0; mi < 4; ++mi) {
        const int row = m0 + wm * 64 + mi * 16 + g;
        #pragma unroll
        for (int ni = 0; ni < 4; ++ni) {
            const int col = n0 + wn * 32 + ni * 8 + tig * 2;
            float b0v = bias[col], b1v = bias[col + 1];
            float v00 = acc[mi][ni][0] + b0v, v01 = acc[mi][ni][1] + b1v;
            float v10 = acc[mi][ni][2] + b0v, v11 = acc[mi][ni][3] + b1v;
            if (do_split) {
                float sc = (col < scale_cols) ? 0.125f : 1.0f;
                *reinterpret_cast<uint32_t*>(&Chi[(size_t)row * N + col]) =
                    pack_half2(v00 * sc, v01 * sc);
                *reinterpret_cast<uint32_t*>(&Chi[(size_t)(row + 8) * N + col]) =
                    pack_half2(v10 * sc, v11 * sc);
            } else {
                float2 va = {v00, v01}, vb = {v10, v11};
                *reinterpret_cast<float2*>(&C[(size_t)row * N + col]) = va;
                *reinterpret_cast<float2*>(&C[(size_t)(row + 8) * N + col]) = vb;
            }
        }
    }
}

// ---------------------------------------------------------------------------
// Tensor-core flash attention, pure fp16 single pass.
// CTA = (q-tile 128, h, t); 8 warps, warp = 16 query rows.
// S = Q.K^T ; softmax fp32 ; O += P.V. P in registers (C-frag == A-frag).
// ---------------------------------------------------------------------------
#define ARS 144

__global__ __launch_bounds__(256) void attn_mma_kernel()
{
    extern __shared__ char smem[];
    const uint32_t sb = smem_u32(smem);
    const int tid = threadIdx.x, lane = tid & 31, wid = tid >> 5;
    const int qt = blockIdx.x, h = blockIdx.y, t = blockIdx.z;
    const int q0 = qt * 128;
    const size_t trow = (size_t)t * B_;

    const __half* qhg  = g_qkv + (trow + q0) * E3_ + h * HD_;
    const __half* khg0 = g_qkv + trow * E3_ + D_ + h * HD_;
    const __half* vhg0 = g_qkv + trow * E3_ + 2 * D_ + h * HD_;

    const int QH = 0;
    const int KH = 0, VH = 64 * ARS;

    // stage Q: 128 rows x 8 chunks of 16B = 1024 float4s (4 iters x 256 thr)
    #pragma unroll
    for (int it = 0; it < 4; ++it) {
        int f = it * 256 + tid, r = f >> 3, c = f & 7;
        *(float4*)(smem + QH + r * ARS + c * 16) = *(const float4*)(qhg + (size_t)r * E3_ + c * 8);
    }
    __syncthreads();

    const int lrow  = ((lane >> 3) & 1) * 8 + (lane & 7);
    const int lkoff = (lane >> 4) * 16;
    uint32_t qfh[4][4];
    {
        const uint32_t qa = sb + (uint32_t)(wid * 16 + lrow) * ARS + lkoff;
        #pragma unroll
        for (int ks = 0; ks < 4; ++ks)
            ldsm4(qfh[ks], qa + QH + ks * 32);
    }
    __syncthreads();   // Q regs extracted; smem reusable for K/V

    float oacc[8][4] = {};
    float mr0 = -1e30f, mr1 = -1e30f, lr0 = 0.f, lr1 = 0.f;

    for (int kt = 0; kt < 8; ++kt) {
        const __half* khg = khg0 + (size_t)kt * 64 * E3_;
        const __half* vhg = vhg0 + (size_t)kt * 64 * E3_;

        // K tile: 64 rows x 8 chunks = 512 float4s (2 iters)
        #pragma unroll
        for (int it = 0; it < 2; ++it) {
            int f = it * 256 + tid, r = f >> 3, c = f & 7;
            *(float4*)(smem + KH + r * ARS + c * 16) = *(const float4*)(khg + (size_t)r * E3_ + c * 8);
        }
        // V tile transposed to hd-major
        #pragma unroll
        for (int it = 0; it < 4; ++it) {
            int idx = it * 256 + tid, s = idx & 31, c = idx >> 5;
            uint32_t u0 = *(const uint32_t*)(vhg + (size_t)(2 * s) * E3_ + 2 * c);
            uint32_t u1 = *(const uint32_t*)(vhg + (size_t)(2 * s + 1) * E3_ + 2 * c);
            *(uint32_t*)(smem + VH + (2 * c) * ARS + s * 4)     = (u0 & 0xFFFFu) | (u1 << 16);
            *(uint32_t*)(smem + VH + (2 * c + 1) * ARS + s * 4) = (u0 >> 16) | (u1 & 0xFFFF0000u);
        }
        __syncthreads();

        // S = Q K^T
        float sacc[8][4] = {};
        #pragma unroll
        for (int ks = 0; ks < 4; ++ks) {
            uint32_t kfh[4][4];
            #pragma unroll
            for (int ng = 0; ng < 4; ++ng) {
                const uint32_t ka = sb + (uint32_t)(ng * 16 + lrow) * ARS + lkoff + ks * 32;
                ldsm4(kfh[ng], ka + KH);
            }
            #pragma unroll
            for (int ng = 0; ng < 4; ++ng)
                #pragma unroll
                for (int sub = 0; sub < 2; ++sub)
                    mma16816(sacc[ng * 2 + sub], qfh[ks], kfh[ng][sub], kfh[ng][sub + 2]);
        }

        // online softmax
        float mx0 = -1e30f, mx1 = -1e30f;
        #pragma unroll
        for (int ni = 0; ni < 8; ++ni) {
            mx0 = fmaxf(mx0, fmaxf(sacc[ni][0], sacc[ni][1]));
            mx1 = fmaxf(mx1, fmaxf(sacc[ni][2], sacc[ni][3]));
        }
        mx0 = fmaxf(mx0, __shfl_xor_sync(0xffffffffu, mx0, 1));
        mx0 = fmaxf(mx0, __shfl_xor_sync(0xffffffffu, mx0, 2));
        mx1 = fmaxf(mx1, __shfl_xor_sync(0xffffffffu, mx1, 1));
        mx1 = fmaxf(mx1, __shfl_xor_sync(0xffffffffu, mx1, 2));
        const float nm0 = fmaxf(mr0, mx0), nm1 = fmaxf(mr1, mx1);
        const float a0 = __expf(mr0 - nm0), a1 = __expf(mr1 - nm1);
        mr0 = nm0; mr1 = nm1;

        uint32_t phA[8], phB[8];
        float rs0 = 0.f, rs1 = 0.f;
        #pragma unroll
        for (int ni = 0; ni < 8; ++ni) {
            float e0 = __expf(sacc[ni][0] - nm0), e1 = __expf(sacc[ni][1] - nm0);
            float e2 = __expf(sacc[ni][2] - nm1), e3 = __expf(sacc[ni][3] - nm1);
            rs0 += e0 + e1; rs1 += e2 + e3;
            phA[ni] = pack_half2(e0, e1);
            phB[ni] = pack_half2(e2, e3);
            oacc[ni][0] *= a0; oacc[ni][1] *= a0;
            oacc[ni][2] *= a1; oacc[ni][3] *= a1;
        }
        rs0 += __shfl_xor_sync(0xffffffffu, rs0, 1);
        rs0 += __shfl_xor_sync(0xffffffffu, rs0, 2);
        rs1 += __shfl_xor_sync(0xffffffffu, rs1, 1);
        rs1 += __shfl_xor_sync(0xffffffffu, rs1, 2);
        lr0 = lr0 * a0 + rs0;
        lr1 = lr1 * a1 + rs1;

        // O += P V
        #pragma unroll
        for (int j = 0; j < 4; ++j) {
            uint32_t vfh[4][4];
            #pragma unroll
            for (int ng = 0; ng < 4; ++ng) {
                const uint32_t va = sb + (uint32_t)(ng * 16 + lrow) * ARS + lkoff + j * 32;
                ldsm4(vfh[ng], va + VH);
            }
            uint32_t aph[4] = {phA[2*j], phB[2*j], phA[2*j+1], phB[2*j+1]};
            #pragma unroll
            for (int ng = 0; ng < 4; ++ng)
                #pragma unroll
                for (int sub = 0; sub < 2; ++sub)
                    mma16816(oacc[ng * 2 + sub], aph, vfh[ng][sub], vfh[ng][sub + 2]);
        }
        __syncthreads();
    }

    // epilogue: normalize by l, write ctx fp16
    const float inv0 = 1.f / lr0, inv1 = 1.f / lr1;
    const int r0 = q0 + wid * 16 + (lane >> 2);
    const int col0 = h * HD_ + (lane & 3) * 2;
    __half* chg = g_ctx + (trow + r0) * D_ + col0;
    #pragma unroll
    for (int ni = 0; ni < 8; ++ni) {
        *reinterpret_cast<uint32_t*>(chg + ni * 8) =
            pack_half2(oacc[ni][0] * inv0, oacc[ni][1] * inv0);
        *reinterpret_cast<uint32_t*>(chg + 8 * D_ + ni * 8) =
            pack_half2(oacc[ni][2] * inv1, oacc[ni][3] * inv1);
    }
}

// ---------------------------------------------------------------------------
// Epilogue reductions
// ---------------------------------------------------------------------------
__device__ __forceinline__ float block_reduce_sum(float v, float* sbuf)
{
    int lane = threadIdx.x & 31, w = threadIdx.x >> 5;
    #pragma unroll
    for (int o = 16; o; o >>= 1) v += __shfl_xor_sync(0xffffffffu, v, o);
    if (lane == 0) sbuf[w] = v;
    __syncthreads();
    float s = (threadIdx.x < (blockDim.x >> 5)) ? sbuf[threadIdx.x] : 0.f;
    if (w == 0) {
        #pragma unroll
        for (int o = 4; o; o >>= 1) s += __shfl_xor_sync(0xffffffffu, s, o);
        if (lane == 0) sbuf[0] = s;
    }
    __syncthreads();
    return sbuf[0];
}

__global__ __launch_bounds__(256) void normalize_kernel()
{
    __shared__ float sbuf[32];
    int row = blockIdx.x;
    float* x = g_out + (size_t)row * D_;
    float s = 0.f;
    for (int i = threadIdx.x; i < D_; i += 256) { float v = x[i]; s += v * v; }
    s = block_reduce_sum(s, sbuf);
    float inv = 1.f / fmaxf(sqrtf(s), 1e-8f);
    for (int i = threadIdx.x; i < D_; i += 256) x[i] *= inv;
}

__global__ __launch_bounds__(256) void mean_kernel()
{
    int t = blockIdx.y;
    int d = blockIdx.x * 256 + threadIdx.x;
    const float* base = g_out + (size_t)t * B_ * D_ + d;
    float s = 0.f;
    for (int b = 0; b < B_; ++b) s += base[(size_t)b * D_];
    g_mean[t * D_ + d] = s * (1.f / B_);
}

__global__ __launch_bounds__(256) void adj_kernel(float* __restrict__ outp)
{
    __shared__ float sbuf[32];
    int row = blockIdx.x;
    int t = row / B_;
    const float* x = g_out + (size_t)row * D_;
    const float* m = g_mean + t * D_;
    float s = 0.f;
    for (int i = threadIdx.x; i < D_; i += 256) s += x[i] * m[i];
    s = block_reduce_sum(s, sbuf);
    if (threadIdx.x == 0) outp[row] = s;
}

// ---------------------------------------------------------------------------

extern "C" void kernel_launch(void* const* d_in, const int* in_sizes, int n_in,
                              void* d_out, int out_size)
{
    const float* node = (const float*)d_in[0];
    const float* w1   = (const float*)d_in[1];
    const float* b1   = (const float*)d_in[2];
    const float* w2   = (const float*)d_in[3];
    const float* b2   = (const float*)d_in[4];
    float* outp = (float*)d_out;

    float* outb;
    cudaGetSymbolAddress((void**)&outb, g_out);
    __half *qkv, *nodeh, *ctxh, *w1h, *w2h;
    cudaGetSymbolAddress((void**)&qkv,   g_qkv);
    cudaGetSymbolAddress((void**)&nodeh, g_node);
    cudaGetSymbolAddress((void**)&ctxh,  g_ctx);
    cudaGetSymbolAddress((void**)&w1h,   g_w1);
    cudaGetSymbolAddress((void**)&w2h,   g_w2);

    const int gemm_smem = 2 * SOFF;        // 40960 B
    const int attn_smem = 128 * ARS;       // 18432 B (Q phase; K|V phase fits too)
    cudaFuncSetAttribute(gemm_mma, cudaFuncAttributeMaxDynamicSharedMemorySize, gemm_smem);
    cudaFuncSetAttribute(attn_mma_kernel, cudaFuncAttributeMaxDynamicSharedMemorySize, attn_smem);

    // convert inputs to fp16
    {
        int n4 = NROWS * D_ / 4;
        cvt_kernel<<<(n4 + 255)/256, 256>>>((const float4*)node, (__half2*)nodeh, n4);
        int w14 = E3_ * D_ / 4;
        cvt_kernel<<<(w14 + 255)/256, 256>>>((const float4*)w1, (__half2*)w1h, w14);
        int w24 = D_ * D_ / 4;
        cvt_kernel<<<(w24 + 255)/256, 256>>>((const float4*)w2, (__half2*)w2h, w24);
    }

    // 1. QKV projection -> fp16 qkv (q cols pre-scaled by 0.125)
    gemm_mma<<<dim3(E3_/128, NROWS/128), 256, gemm_smem>>>(
        nodeh, w1h, b1, nullptr, qkv, E3_, 1, D_);

    // 2. Tensor-core flash attention -> ctx fp16
    attn_mma_kernel<<<dim3(B_/128, H_, T_), 256, attn_smem>>>();

    // 3. Out projection -> fp32 g_out
    gemm_mma<<<dim3(D_/128, NROWS/128), 256, gemm_smem>>>(
        ctxh, w2h, b2, outb, nullptr, D_, 0, 0);

    // 4. Epilogue
    normalize_kernel<<<NROWS, 256>>>();
    mean_kernel<<<dim3(D_/256, T_), 256>>>();
    adj_kernel<<<NROWS, 256>>>(outp);
}

// round 9
// speedup vs baseline: 2.0936x; 2.0936x over previous
#include <cuda_runtime.h>
#include <cuda_fp16.h>
#include <math.h>
#include <stdint.h>

#define T_   64
#define B_   512
#define D_   768
#define H_   12
#define HD_  64
#define E3_  2304
#define NROWS (T_*B_)

// scratch
__device__ __align__(256) float g_out[(size_t)NROWS * D_];
__device__ __align__(256) float g_mean[T_ * D_];
__device__ __align__(256) __half g_qkv[(size_t)NROWS * E3_];
__device__ __align__(256) __half g_node[(size_t)NROWS * D_];
__device__ __align__(256) __half g_ctx [(size_t)NROWS * D_];
__device__ __align__(256) __half g_w1[(size_t)E3_ * D_];
__device__ __align__(256) __half g_w2[(size_t)D_ * D_];

__device__ __forceinline__ uint32_t smem_u32(const void* p) {
    uint32_t a;
    asm("{ .reg .u64 t; cvta.to.shared.u64 t, %1; cvt.u32.u64 %0, t; }" : "=r"(a) : "l"(p));
    return a;
}
__device__ __forceinline__ void cp_async16(uint32_t s, const void* g) {
    asm volatile("cp.async.cg.shared.global [%0], [%1], 16;" :: "r"(s), "l"(g) : "memory");
}
__device__ __forceinline__ void cp_commit() { asm volatile("cp.async.commit_group;" ::: "memory"); }
__device__ __forceinline__ void cp_wait1()  { asm volatile("cp.async.wait_group 1;" ::: "memory"); }
__device__ __forceinline__ void cp_wait0()  { asm volatile("cp.async.wait_group 0;" ::: "memory"); }
__device__ __forceinline__ void ldsm4(uint32_t* r, uint32_t addr) {
    asm volatile("ldmatrix.sync.aligned.m8n8.x4.shared.b16 {%0,%1,%2,%3}, [%4];"
                 : "=r"(r[0]), "=r"(r[1]), "=r"(r[2]), "=r"(r[3]) : "r"(addr));
}
__device__ __forceinline__ void ldsm4t(uint32_t* r, uint32_t addr) {
    asm volatile("ldmatrix.sync.aligned.m8n8.x4.trans.shared.b16 {%0,%1,%2,%3}, [%4];"
                 : "=r"(r[0]), "=r"(r[1]), "=r"(r[2]), "=r"(r[3]) : "r"(addr));
}
__device__ __forceinline__ void mma16816(float* d, const uint32_t* a, uint32_t b0, uint32_t b1) {
    asm volatile(
        "mma.sync.aligned.m16n8k16.row.col.f32.f16.f16.f32 "
        "{%0,%1,%2,%3}, {%4,%5,%6,%7}, {%8,%9}, {%0,%1,%2,%3};"
        : "+f"(d[0]), "+f"(d[1]), "+f"(d[2]), "+f"(d[3])
        : "r"(a[0]), "r"(a[1]), "r"(a[2]), "r"(a[3]), "r"(b0), "r"(b1));
}
__device__ __forceinline__ uint32_t pack_half2(float a, float b) {
    __half2 h = __floats2half2_rn(a, b);
    return *reinterpret_cast<uint32_t*>(&h);
}

// ---------------------------------------------------------------------------
// fp32 -> fp16 convert
// ---------------------------------------------------------------------------
__global__ __launch_bounds__(256) void cvt_kernel(
    const float4* __restrict__ x, __half2* __restrict__ hi, int n4)
{
    int i = blockIdx.x * 256 + threadIdx.x;
    if (i >= n4) return;
    float4 v = x[i];
    hi[2*i]   = __half2(__float2half_rn(v.x), __float2half_rn(v.y));
    hi[2*i+1] = __half2(__float2half_rn(v.z), __float2half_rn(v.w));
}

// ---------------------------------------------------------------------------
// mma.sync fp16 GEMM, BK=64: C[m,n] = bias[n] + sum_k A[m,k]*W[n,k], K=768.
// 128x128 CTA tile, 12 iterations, 2-stage cp.async, 8 warps (2m x 4n).
// smem: 2 stages x 2 tiles x 18432B = 73728 B. 2 CTAs/SM.
// ---------------------------------------------------------------------------
#define RS   144
#define TOFF (128*144)     // 18432
#define SOFF (2*TOFF)      // 36864 per stage

__global__ __launch_bounds__(256, 2) void gemm_mma(
    const __half* __restrict__ Ahi, const __half* __restrict__ Bhi,
    const float* __restrict__ bias, float* __restrict__ C,
    __half* __restrict__ Chi,
    int N, int do_split, int scale_cols)
{
    extern __shared__ char smem[];
    const uint32_t sb = smem_u32(smem);
    const int tid = threadIdx.x;
    const int wid = tid >> 5, lane = tid & 31;
    const int wm = wid & 1, wn = wid >> 1;
    const int m0 = blockIdx.y * 128;
    const int n0 = blockIdx.x * 128;

    const __half* srcs[2] = {Ahi, Bhi};
    const int r0s[2] = {m0, n0};
    const int crow = tid >> 3;          // 0..31
    const int cc   = tid & 7;           // 8 chunks of 16B per 128B row

    float acc[4][4][4] = {};

    const int lrow  = ((lane >> 3) & 1) * 8 + (lane & 7);
    const int lkoff = (lane >> 4) * 16;
    const uint32_t a_base = sb + (uint32_t)(wm * 64 + lrow) * RS + lkoff;
    const uint32_t b_base = sb + (uint32_t)(wn * 32 + lrow) * RS + lkoff + TOFF;

    // prologue: stage 0 (k0 = 0)
    {
        #pragma unroll
        for (int tI = 0; tI < 2; ++tI)
            #pragma unroll
            for (int it = 0; it < 4; ++it) {
                int row = crow + it * 32;
                cp_async16(sb + tI * TOFF + row * RS + cc * 16,
                           srcs[tI] + (size_t)(r0s[tI] + row) * D_ + cc * 8);
            }
        cp_commit();
    }

    for (int c = 0; c < 12; ++c) {
        if (c < 11) {
            const int k0 = (c + 1) * 64;
            const uint32_t base = sb + ((c + 1) & 1) * SOFF;
            #pragma unroll
            for (int tI = 0; tI < 2; ++tI)
                #pragma unroll
                for (int it = 0; it < 4; ++it) {
                    int row = crow + it * 32;
                    cp_async16(base + tI * TOFF + row * RS + cc * 16,
                               srcs[tI] + (size_t)(r0s[tI] + row) * D_ + k0 + cc * 8);
                }
            cp_commit();
            cp_wait1();
        } else {
            cp_wait0();
        }
        __syncthreads();

        const uint32_t st = ((uint32_t)(c & 1)) * SOFF;
        #pragma unroll
        for (int ks = 0; ks < 4; ++ks) {
            const uint32_t ko = ks * 32;
            uint32_t ah[4][4], bh[2][4];
            #pragma unroll
            for (int mi = 0; mi < 4; ++mi)
                ldsm4(ah[mi], a_base + st + mi * 16 * RS + ko);
            #pragma unroll
            for (int nt = 0; nt < 2; ++nt)
                ldsm4(bh[nt], b_base + st + nt * 16 * RS + ko);
            #pragma unroll
            for (int mi = 0; mi < 4; ++mi)
                #pragma unroll
                for (int ni = 0; ni < 4; ++ni) {
                    const int nt = ni >> 1, hl = ni & 1;
                    mma16816(acc[mi][ni], ah[mi], bh[nt][hl], bh[nt][hl + 2]);
                }
        }
        __syncthreads();
    }

    const int g   = lane >> 2;
    const int tig = lane & 3;
    #pragma unroll
    for (int mi = 0; mi < 4; ++mi) {
        const int row = m0 + wm * 64 + mi * 16 + g;
        #pragma unroll
        for (int ni = 0; ni < 4; ++ni) {
            const int col = n0 + wn * 32 + ni * 8 + tig * 2;
            float b0v = bias[col], b1v = bias[col + 1];
            float v00 = acc[mi][ni][0] + b0v, v01 = acc[mi][ni][1] + b1v;
            float v10 = acc[mi][ni][2] + b0v, v11 = acc[mi][ni][3] + b1v;
            if (do_split) {
                float sc = (col < scale_cols) ? 0.125f : 1.0f;
                *reinterpret_cast<uint32_t*>(&Chi[(size_t)row * N + col]) =
                    pack_half2(v00 * sc, v01 * sc);
                *reinterpret_cast<uint32_t*>(&Chi[(size_t)(row + 8) * N + col]) =
                    pack_half2(v10 * sc, v11 * sc);
            } else {
                float2 va = {v00, v01}, vb = {v10, v11};
                *reinterpret_cast<float2*>(&C[(size_t)row * N + col]) = va;
                *reinterpret_cast<float2*>(&C[(size_t)(row + 8) * N + col]) = vb;
            }
        }
    }
}

// ---------------------------------------------------------------------------
// Tensor-core flash attention, fp16 single pass, cp.async double-buffered K/V.
// V stored K-major in smem; PV B-fragments via ldmatrix.trans (no scalar
// transpose, fully coalesced V loads).
// smem: Q 18432 | KV stage0 18432 (K 9216 + V 9216) | KV stage1 18432.
// ---------------------------------------------------------------------------
#define ARS 144
#define AKV_OFF 18432
#define AKV_STRIDE 18432
#define AV_OFF 9216
#define ATTN_SMEM (AKV_OFF + 2 * AKV_STRIDE)   // 55296

__global__ __launch_bounds__(256) void attn_mma_kernel()
{
    extern __shared__ char smem[];
    const uint32_t sb = smem_u32(smem);
    const int tid = threadIdx.x, lane = tid & 31, wid = tid >> 5;
    const int qt = blockIdx.x, h = blockIdx.y, t = blockIdx.z;
    const int q0 = qt * 128;
    const size_t trow = (size_t)t * B_;

    const __half* qhg  = g_qkv + (trow + q0) * E3_ + h * HD_;
    const __half* khg0 = g_qkv + trow * E3_ + D_ + h * HD_;
    const __half* vhg0 = g_qkv + trow * E3_ + 2 * D_ + h * HD_;

    auto load_kv = [&](int kt_) {
        const __half* kptr = khg0 + (size_t)kt_ * 64 * E3_;
        const __half* vptr = vhg0 + (size_t)kt_ * 64 * E3_;
        const uint32_t base = sb + AKV_OFF + (uint32_t)(kt_ & 1) * AKV_STRIDE;
        #pragma unroll
        for (int it = 0; it < 2; ++it) {
            int f = it * 256 + tid, r = f >> 3, c = f & 7;
            cp_async16(base + r * ARS + c * 16, kptr + (size_t)r * E3_ + c * 8);
            cp_async16(base + AV_OFF + r * ARS + c * 16, vptr + (size_t)r * E3_ + c * 8);
        }
        cp_commit();
    };

    // start KV stage 0 immediately
    load_kv(0);

    // stage Q: 128 rows x 8 chunks (plain stores, overlap with cp.async)
    #pragma unroll
    for (int it = 0; it < 4; ++it) {
        int f = it * 256 + tid, r = f >> 3, c = f & 7;
        *(float4*)(smem + r * ARS + c * 16) = *(const float4*)(qhg + (size_t)r * E3_ + c * 8);
    }
    __syncthreads();

    const int lrow  = ((lane >> 3) & 1) * 8 + (lane & 7);
    const int lkoff = (lane >> 4) * 16;
    uint32_t qfh[4][4];
    {
        const uint32_t qa = sb + (uint32_t)(wid * 16 + lrow) * ARS + lkoff;
        #pragma unroll
        for (int ks = 0; ks < 4; ++ks)
            ldsm4(qfh[ks], qa + ks * 32);
    }

    float oacc[8][4] = {};
    float mr0 = -1e30f, mr1 = -1e30f, lr0 = 0.f, lr1 = 0.f;

    for (int kt = 0; kt < 8; ++kt) {
        if (kt < 7) { load_kv(kt + 1); cp_wait1(); }
        else        { cp_wait0(); }
        __syncthreads();

        const uint32_t stg = sb + AKV_OFF + (uint32_t)(kt & 1) * AKV_STRIDE;

        // S = Q K^T
        float sacc[8][4] = {};
        #pragma unroll
        for (int ks = 0; ks < 4; ++ks) {
            uint32_t kfh[4][4];
            #pragma unroll
            for (int ng = 0; ng < 4; ++ng)
                ldsm4(kfh[ng], stg + (uint32_t)(ng * 16 + lrow) * ARS + lkoff + ks * 32);
            #pragma unroll
            for (int ng = 0; ng < 4; ++ng)
                #pragma unroll
                for (int sub = 0; sub < 2; ++sub)
                    mma16816(sacc[ng * 2 + sub], qfh[ks], kfh[ng][sub], kfh[ng][sub + 2]);
        }

        // online softmax
        float mx0 = -1e30f, mx1 = -1e30f;
        #pragma unroll
        for (int ni = 0; ni < 8; ++ni) {
            mx0 = fmaxf(mx0, fmaxf(sacc[ni][0], sacc[ni][1]));
            mx1 = fmaxf(mx1, fmaxf(sacc[ni][2], sacc[ni][3]));
        }
        mx0 = fmaxf(mx0, __shfl_xor_sync(0xffffffffu, mx0, 1));
        mx0 = fmaxf(mx0, __shfl_xor_sync(0xffffffffu, mx0, 2));
        mx1 = fmaxf(mx1, __shfl_xor_sync(0xffffffffu, mx1, 1));
        mx1 = fmaxf(mx1, __shfl_xor_sync(0xffffffffu, mx1, 2));
        const float nm0 = fmaxf(mr0, mx0), nm1 = fmaxf(mr1, mx1);
        const float a0 = __expf(mr0 - nm0), a1 = __expf(mr1 - nm1);
        mr0 = nm0; mr1 = nm1;

        uint32_t phA[8], phB[8];
        float rs0 = 0.f, rs1 = 0.f;
        #pragma unroll
        for (int ni = 0; ni < 8; ++ni) {
            float e0 = __expf(sacc[ni][0] - nm0), e1 = __expf(sacc[ni][1] - nm0);
            float e2 = __expf(sacc[ni][2] - nm1), e3 = __expf(sacc[ni][3] - nm1);
            rs0 += e0 + e1; rs1 += e2 + e3;
            phA[ni] = pack_half2(e0, e1);
            phB[ni] = pack_half2(e2, e3);
            oacc[ni][0] *= a0; oacc[ni][1] *= a0;
            oacc[ni][2] *= a1; oacc[ni][3] *= a1;
        }
        rs0 += __shfl_xor_sync(0xffffffffu, rs0, 1);
        rs0 += __shfl_xor_sync(0xffffffffu, rs0, 2);
        rs1 += __shfl_xor_sync(0xffffffffu, rs1, 1);
        rs1 += __shfl_xor_sync(0xffffffffu, rs1, 2);
        lr0 = lr0 * a0 + rs0;
        lr1 = lr1 * a1 + rs1;

        // O += P V  (V K-major; B-frags via ldmatrix.trans)
        #pragma unroll
        for (int j = 0; j < 4; ++j) {
            uint32_t aph[4] = {phA[2*j], phB[2*j], phA[2*j+1], phB[2*j+1]};
            #pragma unroll
            for (int ng = 0; ng < 4; ++ng) {
                uint32_t vf[4];
                ldsm4t(vf, stg + AV_OFF + (uint32_t)(j * 16 + lrow) * ARS + ng * 32 + lkoff);
                mma16816(oacc[ng * 2 + 0], aph, vf[0], vf[1]);
                mma16816(oacc[ng * 2 + 1], aph, vf[2], vf[3]);
            }
        }
        __syncthreads();
    }

    // epilogue: normalize by l, write ctx fp16
    const float inv0 = 1.f / lr0, inv1 = 1.f / lr1;
    const int r0 = q0 + wid * 16 + (lane >> 2);
    const int col0 = h * HD_ + (lane & 3) * 2;
    __half* chg = g_ctx + (trow + r0) * D_ + col0;
    #pragma unroll
    for (int ni = 0; ni < 8; ++ni) {
        *reinterpret_cast<uint32_t*>(chg + ni * 8) =
            pack_half2(oacc[ni][0] * inv0, oacc[ni][1] * inv0);
        *reinterpret_cast<uint32_t*>(chg + 8 * D_ + ni * 8) =
            pack_half2(oacc[ni][2] * inv1, oacc[ni][3] * inv1);
    }
}

// ---------------------------------------------------------------------------
// Epilogue reductions
// ---------------------------------------------------------------------------
__device__ __forceinline__ float block_reduce_sum(float v, float* sbuf)
{
    int lane = threadIdx.x & 31, w = threadIdx.x >> 5;
    #pragma unroll
    for (int o = 16; o; o >>= 1) v += __shfl_xor_sync(0xffffffffu, v, o);
    if (lane == 0) sbuf[w] = v;
    __syncthreads();
    float s = (threadIdx.x < (blockDim.x >> 5)) ? sbuf[threadIdx.x] : 0.f;
    if (w == 0) {
        #pragma unroll
        for (int o = 4; o; o >>= 1) s += __shfl_xor_sync(0xffffffffu, s, o);
        if (lane == 0) sbuf[0] = s;
    }
    __syncthreads();
    return sbuf[0];
}

__global__ __launch_bounds__(256) void normalize_kernel()
{
    __shared__ float sbuf[32];
    int row = blockIdx.x;
    float* x = g_out + (size_t)row * D_;
    float s = 0.f;
    for (int i = threadIdx.x; i < D_; i += 256) { float v = x[i]; s += v * v; }
    s = block_reduce_sum(s, sbuf);
    float inv = 1.f / fmaxf(sqrtf(s), 1e-8f);
    for (int i = threadIdx.x; i < D_; i += 256) x[i] *= inv;
}

__global__ __launch_bounds__(256) void mean_kernel()
{
    int t = blockIdx.y;
    int d = blockIdx.x * 256 + threadIdx.x;
    const float* base = g_out + (size_t)t * B_ * D_ + d;
    float s = 0.f;
    for (int b = 0; b < B_; ++b) s += base[(size_t)b * D_];
    g_mean[t * D_ + d] = s * (1.f / B_);
}

__global__ __launch_bounds__(256) void adj_kernel(float* __restrict__ outp)
{
    __shared__ float sbuf[32];
    int row = blockIdx.x;
    int t = row / B_;
    const float* x = g_out + (size_t)row * D_;
    const float* m = g_mean + t * D_;
    float s = 0.f;
    for (int i = threadIdx.x; i < D_; i += 256) s += x[i] * m[i];
    s = block_reduce_sum(s, sbuf);
    if (threadIdx.x == 0) outp[row] = s;
}

// ---------------------------------------------------------------------------

extern "C" void kernel_launch(void* const* d_in, const int* in_sizes, int n_in,
                              void* d_out, int out_size)
{
    const float* node = (const float*)d_in[0];
    const float* w1   = (const float*)d_in[1];
    const float* b1   = (const float*)d_in[2];
    const float* w2   = (const float*)d_in[3];
    const float* b2   = (const float*)d_in[4];
    float* outp = (float*)d_out;

    float* outb;
    cudaGetSymbolAddress((void**)&outb, g_out);
    __half *qkv, *nodeh, *ctxh, *w1h, *w2h;
    cudaGetSymbolAddress((void**)&qkv,   g_qkv);
    cudaGetSymbolAddress((void**)&nodeh, g_node);
    cudaGetSymbolAddress((void**)&ctxh,  g_ctx);
    cudaGetSymbolAddress((void**)&w1h,   g_w1);
    cudaGetSymbolAddress((void**)&w2h,   g_w2);

    const int gemm_smem = 2 * SOFF;        // 73728 B
    cudaFuncSetAttribute(gemm_mma, cudaFuncAttributeMaxDynamicSharedMemorySize, gemm_smem);
    cudaFuncSetAttribute(attn_mma_kernel, cudaFuncAttributeMaxDynamicSharedMemorySize, ATTN_SMEM);

    // convert inputs to fp16
    {
        int n4 = NROWS * D_ / 4;
        cvt_kernel<<<(n4 + 255)/256, 256>>>((const float4*)node, (__half2*)nodeh, n4);
        int w14 = E3_ * D_ / 4;
        cvt_kernel<<<(w14 + 255)/256, 256>>>((const float4*)w1, (__half2*)w1h, w14);
        int w24 = D_ * D_ / 4;
        cvt_kernel<<<(w24 + 255)/256, 256>>>((const float4*)w2, (__half2*)w2h, w24);
    }

    // 1. QKV projection -> fp16 qkv (q cols pre-scaled by 0.125)
    gemm_mma<<<dim3(E3_/128, NROWS/128), 256, gemm_smem>>>(
        nodeh, w1h, b1, nullptr, qkv, E3_, 1, D_);

    // 2. Tensor-core flash attention -> ctx fp16
    attn_mma_kernel<<<dim3(B_/128, H_, T_), 256, ATTN_SMEM>>>();

    // 3. Out projection -> fp32 g_out
    gemm_mma<<<dim3(D_/128, NROWS/128), 256, gemm_smem>>>(
        ctxh, w2h, b2, outb, nullptr, D_, 0, 0);

    // 4. Epilogue
    normalize_kernel<<<NROWS, 256>>>();
    mean_kernel<<<dim3(D_/256, T_), 256>>>();
    adj_kernel<<<NROWS, 256>>>(outp);
}

// round 12
// speedup vs baseline: 2.2340x; 1.0671x over previous
#include <cuda_runtime.h>
#include <cuda_fp16.h>
#include <math.h>
#include <stdint.h>

#define T_   64
#define B_   512
#define D_   768
#define H_   12
#define HD_  64
#define E3_  2304
#define NROWS (T_*B_)

// scratch
__device__ __align__(256) float g_out[(size_t)NROWS * D_];
__device__ __align__(256) float g_mean[T_ * D_];
__device__ __align__(256) float g_sumsq[NROWS];
__device__ __align__(256) __half g_qkv[(size_t)NROWS * E3_];
__device__ __align__(256) __half g_node[(size_t)NROWS * D_];
__device__ __align__(256) __half g_ctx [(size_t)NROWS * D_];
__device__ __align__(256) __half g_w1[(size_t)E3_ * D_];
__device__ __align__(256) __half g_w2[(size_t)D_ * D_];

__device__ __forceinline__ uint32_t smem_u32(const void* p) {
    uint32_t a;
    asm("{ .reg .u64 t; cvta.to.shared.u64 t, %1; cvt.u32.u64 %0, t; }" : "=r"(a) : "l"(p));
    return a;
}
__device__ __forceinline__ void cp_async16(uint32_t s, const void* g) {
    asm volatile("cp.async.cg.shared.global [%0], [%1], 16;" :: "r"(s), "l"(g) : "memory");
}
__device__ __forceinline__ void cp_commit() { asm volatile("cp.async.commit_group;" ::: "memory"); }
__device__ __forceinline__ void cp_wait1()  { asm volatile("cp.async.wait_group 1;" ::: "memory"); }
__device__ __forceinline__ void cp_wait0()  { asm volatile("cp.async.wait_group 0;" ::: "memory"); }
__device__ __forceinline__ void ldsm4(uint32_t* r, uint32_t addr) {
    asm volatile("ldmatrix.sync.aligned.m8n8.x4.shared.b16 {%0,%1,%2,%3}, [%4];"
                 : "=r"(r[0]), "=r"(r[1]), "=r"(r[2]), "=r"(r[3]) : "r"(addr));
}
__device__ __forceinline__ void ldsm4t(uint32_t* r, uint32_t addr) {
    asm volatile("ldmatrix.sync.aligned.m8n8.x4.trans.shared.b16 {%0,%1,%2,%3}, [%4];"
                 : "=r"(r[0]), "=r"(r[1]), "=r"(r[2]), "=r"(r[3]) : "r"(addr));
}
__device__ __forceinline__ void mma16816(float* d, const uint32_t* a, uint32_t b0, uint32_t b1) {
    asm volatile(
        "mma.sync.aligned.m16n8k16.row.col.f32.f16.f16.f32 "
        "{%0,%1,%2,%3}, {%4,%5,%6,%7}, {%8,%9}, {%0,%1,%2,%3};"
        : "+f"(d[0]), "+f"(d[1]), "+f"(d[2]), "+f"(d[3])
        : "r"(a[0]), "r"(a[1]), "r"(a[2]), "r"(a[3]), "r"(b0), "r"(b1));
}
__device__ __forceinline__ uint32_t pack_half2(float a, float b) {
    __half2 h = __floats2half2_rn(a, b);
    return *reinterpret_cast<uint32_t*>(&h);
}

// ---------------------------------------------------------------------------
// fp32 -> fp16 convert  +  sumsq zero
// ---------------------------------------------------------------------------
__global__ __launch_bounds__(256) void cvt_kernel(
    const float4* __restrict__ x, __half2* __restrict__ hi, int n4)
{
    int i = blockIdx.x * 256 + threadIdx.x;
    if (i >= n4) return;
    float4 v = x[i];
    hi[2*i]   = __half2(__float2half_rn(v.x), __float2half_rn(v.y));
    hi[2*i+1] = __half2(__float2half_rn(v.z), __float2half_rn(v.w));
}

__global__ __launch_bounds__(256) void zero_kernel()
{
    g_sumsq[blockIdx.x * 256 + threadIdx.x] = 0.f;
}

// ---------------------------------------------------------------------------
// mma.sync fp16 GEMM, BK=64, 3-stage cp.async ring, ONE barrier/iteration.
// C[m,n] = bias[n] + sum_k A[m,k]*W[n,k], K=768. 128x128 CTA tile, 8 warps.
// smem: 3 stages x 2 tiles x 18432B = 110592 B. 2 CTAs/SM.
// do_split=1: fp16 out (cols < scale_cols x0.125). do_split=0: fp32 out +
// per-row sum-of-squares accumulated into g_sumsq via atomics.
// ---------------------------------------------------------------------------
#define RS   144
#define TOFF (128*144)     // 18432
#define SOFF (2*TOFF)      // 36864 per stage

__global__ __launch_bounds__(256, 2) void gemm_mma(
    const __half* __restrict__ Ahi, const __half* __restrict__ Bhi,
    const float* __restrict__ bias, float* __restrict__ C,
    __half* __restrict__ Chi,
    int N, int do_split, int scale_cols)
{
    extern __shared__ char smem[];
    const uint32_t sb = smem_u32(smem);
    const int tid = threadIdx.x;
    const int wid = tid >> 5, lane = tid & 31;
    const int wm = wid & 1, wn = wid >> 1;
    const int m0 = blockIdx.y * 128;
    const int n0 = blockIdx.x * 128;

    const __half* srcs[2] = {Ahi, Bhi};
    const int r0s[2] = {m0, n0};
    const int crow = tid >> 3;          // 0..31
    const int cc   = tid & 7;

    float acc[4][4][4] = {};

    const int lrow  = ((lane >> 3) & 1) * 8 + (lane & 7);
    const int lkoff = (lane >> 4) * 16;
    const uint32_t a_base = sb + (uint32_t)(wm * 64 + lrow) * RS + lkoff;
    const uint32_t b_base = sb + (uint32_t)(wn * 32 + lrow) * RS + lkoff + TOFF;

    auto issue_stage = [&](int c) {
        const int k0 = c * 64;
        const uint32_t base = sb + (uint32_t)(c % 3) * SOFF;
        #pragma unroll
        for (int tI = 0; tI < 2; ++tI)
            #pragma unroll
            for (int it = 0; it < 4; ++it) {
                int row = crow + it * 32;
                cp_async16(base + tI * TOFF + row * RS + cc * 16,
                           srcs[tI] + (size_t)(r0s[tI] + row) * D_ + k0 + cc * 8);
            }
        cp_commit();
    };

    issue_stage(0);
    issue_stage(1);

    for (int c = 0; c < 12; ++c) {
        if (c < 11) cp_wait1(); else cp_wait0();
        __syncthreads();                       // stage c visible; buf (c+2)%3 free
        if (c < 10) issue_stage(c + 2);

        const uint32_t st = (uint32_t)(c % 3) * SOFF;
        #pragma unroll
        for (int ks = 0; ks < 4; ++ks) {
            const uint32_t ko = ks * 32;
            uint32_t ah[4][4], bh[2][4];
            #pragma unroll
            for (int mi = 0; mi < 4; ++mi)
                ldsm4(ah[mi], a_base + st + mi * 16 * RS + ko);
            #pragma unroll
            for (int nt = 0; nt < 2; ++nt)
                ldsm4(bh[nt], b_base + st + nt * 16 * RS + ko);
            #pragma unroll
            for (int mi = 0; mi < 4; ++mi)
                #pragma unroll
                for (int ni = 0; ni < 4; ++ni) {
                    const int nt = ni >> 1, hl = ni & 1;
                    mma16816(acc[mi][ni], ah[mi], bh[nt][hl], bh[nt][hl + 2]);
                }
        }
    }

    const int g   = lane >> 2;
    const int tig = lane & 3;
    #pragma unroll
    for (int mi = 0; mi < 4; ++mi) {
        const int row = m0 + wm * 64 + mi * 16 + g;
        float ss_lo = 0.f, ss_hi = 0.f;
        #pragma unroll
        for (int ni = 0; ni < 4; ++ni) {
            const int col = n0 + wn * 32 + ni * 8 + tig * 2;
            float b0v = bias[col], b1v = bias[col + 1];
            float v00 = acc[mi][ni][0] + b0v, v01 = acc[mi][ni][1] + b1v;
            float v10 = acc[mi][ni][2] + b0v, v11 = acc[mi][ni][3] + b1v;
            if (do_split) {
                float sc = (col < scale_cols) ? 0.125f : 1.0f;
                *reinterpret_cast<uint32_t*>(&Chi[(size_t)row * N + col]) =
                    pack_half2(v00 * sc, v01 * sc);
                *reinterpret_cast<uint32_t*>(&Chi[(size_t)(row + 8) * N + col]) =
                    pack_half2(v10 * sc, v11 * sc);
            } else {
                float2 va = {v00, v01}, vb = {v10, v11};
                *reinterpret_cast<float2*>(&C[(size_t)row * N + col]) = va;
                *reinterpret_cast<float2*>(&C[(size_t)(row + 8) * N + col]) = vb;
                ss_lo += v00 * v00 + v01 * v01;
                ss_hi += v10 * v10 + v11 * v11;
            }
        }
        if (!do_split) {
            ss_lo += __shfl_xor_sync(0xffffffffu, ss_lo, 1);
            ss_lo += __shfl_xor_sync(0xffffffffu, ss_lo, 2);
            ss_hi += __shfl_xor_sync(0xffffffffu, ss_hi, 1);
            ss_hi += __shfl_xor_sync(0xffffffffu, ss_hi, 2);
            if (tig == 0) {
                atomicAdd(&g_sumsq[row], ss_lo);
                atomicAdd(&g_sumsq[row + 8], ss_hi);
            }
        }
    }
}

// ---------------------------------------------------------------------------
// Tensor-core flash attention, fp16, 3-buffer cp.async KV ring, one
// barrier/iteration. V K-major + ldmatrix.trans for PV B-fragments.
// smem: Q 18432 | 3 x KV(18432) = 73728 total.
// ---------------------------------------------------------------------------
#define ARS 144
#define AKV_OFF 18432
#define AKV_STRIDE 18432
#define AV_OFF 9216
#define ATTN_SMEM (AKV_OFF + 3 * AKV_STRIDE)   // 73728

__global__ __launch_bounds__(256) void attn_mma_kernel()
{
    extern __shared__ char smem[];
    const uint32_t sb = smem_u32(smem);
    const int tid = threadIdx.x, lane = tid & 31, wid = tid >> 5;
    const int qt = blockIdx.x, h = blockIdx.y, t = blockIdx.z;
    const int q0 = qt * 128;
    const size_t trow = (size_t)t * B_;

    const __half* qhg  = g_qkv + (trow + q0) * E3_ + h * HD_;
    const __half* khg0 = g_qkv + trow * E3_ + D_ + h * HD_;
    const __half* vhg0 = g_qkv + trow * E3_ + 2 * D_ + h * HD_;

    auto load_kv = [&](int kt_) {
        const __half* kptr = khg0 + (size_t)kt_ * 64 * E3_;
        const __half* vptr = vhg0 + (size_t)kt_ * 64 * E3_;
        const uint32_t base = sb + AKV_OFF + (uint32_t)(kt_ % 3) * AKV_STRIDE;
        #pragma unroll
        for (int it = 0; it < 2; ++it) {
            int f = it * 256 + tid, r = f >> 3, c = f & 7;
            cp_async16(base + r * ARS + c * 16, kptr + (size_t)r * E3_ + c * 8);
            cp_async16(base + AV_OFF + r * ARS + c * 16, vptr + (size_t)r * E3_ + c * 8);
        }
        cp_commit();
    };

    load_kv(0);
    load_kv(1);

    // stage Q (plain stores, overlaps the cp.asyncs)
    #pragma unroll
    for (int it = 0; it < 4; ++it) {
        int f = it * 256 + tid, r = f >> 3, c = f & 7;
        *(float4*)(smem + r * ARS + c * 16) = *(const float4*)(qhg + (size_t)r * E3_ + c * 8);
    }
    __syncthreads();

    const int lrow  = ((lane >> 3) & 1) * 8 + (lane & 7);
    const int lkoff = (lane >> 4) * 16;
    uint32_t qfh[4][4];
    {
        const uint32_t qa = sb + (uint32_t)(wid * 16 + lrow) * ARS + lkoff;
        #pragma unroll
        for (int ks = 0; ks < 4; ++ks)
            ldsm4(qfh[ks], qa + ks * 32);
    }

    float oacc[8][4] = {};
    float mr0 = -1e30f, mr1 = -1e30f, lr0 = 0.f, lr1 = 0.f;

    for (int kt = 0; kt < 8; ++kt) {
        if (kt < 7) cp_wait1(); else cp_wait0();
        __syncthreads();                      // stage kt visible; buf (kt+2)%3 free
        if (kt < 6) load_kv(kt + 2);

        const uint32_t stg = sb + AKV_OFF + (uint32_t)(kt % 3) * AKV_STRIDE;

        // S = Q K^T
        float sacc[8][4] = {};
        #pragma unroll
        for (int ks = 0; ks < 4; ++ks) {
            uint32_t kfh[4][4];
            #pragma unroll
            for (int ng = 0; ng < 4; ++ng)
                ldsm4(kfh[ng], stg + (uint32_t)(ng * 16 + lrow) * ARS + lkoff + ks * 32);
            #pragma unroll
            for (int ng = 0; ng < 4; ++ng)
                #pragma unroll
                for (int sub = 0; sub < 2; ++sub)
                    mma16816(sacc[ng * 2 + sub], qfh[ks], kfh[ng][sub], kfh[ng][sub + 2]);
        }

        // online softmax
        float mx0 = -1e30f, mx1 = -1e30f;
        #pragma unroll
        for (int ni = 0; ni < 8; ++ni) {
            mx0 = fmaxf(mx0, fmaxf(sacc[ni][0], sacc[ni][1]));
            mx1 = fmaxf(mx1, fmaxf(sacc[ni][2], sacc[ni][3]));
        }
        mx0 = fmaxf(mx0, __shfl_xor_sync(0xffffffffu, mx0, 1));
        mx0 = fmaxf(mx0, __shfl_xor_sync(0xffffffffu, mx0, 2));
        mx1 = fmaxf(mx1, __shfl_xor_sync(0xffffffffu, mx1, 1));
        mx1 = fmaxf(mx1, __shfl_xor_sync(0xffffffffu, mx1, 2));
        const float nm0 = fmaxf(mr0, mx0), nm1 = fmaxf(mr1, mx1);
        const float a0 = __expf(mr0 - nm0), a1 = __expf(mr1 - nm1);
        mr0 = nm0; mr1 = nm1;

        uint32_t phA[8], phB[8];
        float rs0 = 0.f, rs1 = 0.f;
        #pragma unroll
        for (int ni = 0; ni < 8; ++ni) {
            float e0 = __expf(sacc[ni][0] - nm0), e1 = __expf(sacc[ni][1] - nm0);
            float e2 = __expf(sacc[ni][2] - nm1), e3 = __expf(sacc[ni][3] - nm1);
            rs0 += e0 + e1; rs1 += e2 + e3;
            phA[ni] = pack_half2(e0, e1);
            phB[ni] = pack_half2(e2, e3);
            oacc[ni][0] *= a0; oacc[ni][1] *= a0;
            oacc[ni][2] *= a1; oacc[ni][3] *= a1;
        }
        rs0 += __shfl_xor_sync(0xffffffffu, rs0, 1);
        rs0 += __shfl_xor_sync(0xffffffffu, rs0, 2);
        rs1 += __shfl_xor_sync(0xffffffffu, rs1, 1);
        rs1 += __shfl_xor_sync(0xffffffffu, rs1, 2);
        lr0 = lr0 * a0 + rs0;
        lr1 = lr1 * a1 + rs1;

        // O += P V  (V K-major; B-frags via ldmatrix.trans)
        #pragma unroll
        for (int j = 0; j < 4; ++j) {
            uint32_t aph[4] = {phA[2*j], phB[2*j], phA[2*j+1], phB[2*j+1]};
            #pragma unroll
            for (int ng = 0; ng < 4; ++ng) {
                uint32_t vf[4];
                ldsm4t(vf, stg + AV_OFF + (uint32_t)(j * 16 + lrow) * ARS + ng * 32 + lkoff);
                mma16816(oacc[ng * 2 + 0], aph, vf[0], vf[1]);
                mma16816(oacc[ng * 2 + 1], aph, vf[2], vf[3]);
            }
        }
    }

    // epilogue: normalize by l, write ctx fp16
    const float inv0 = 1.f / lr0, inv1 = 1.f / lr1;
    const int r0 = q0 + wid * 16 + (lane >> 2);
    const int col0 = h * HD_ + (lane & 3) * 2;
    __half* chg = g_ctx + (trow + r0) * D_ + col0;
    #pragma unroll
    for (int ni = 0; ni < 8; ++ni) {
        *reinterpret_cast<uint32_t*>(chg + ni * 8) =
            pack_half2(oacc[ni][0] * inv0, oacc[ni][1] * inv0);
        *reinterpret_cast<uint32_t*>(chg + 8 * D_ + ni * 8) =
            pack_half2(oacc[ni][2] * inv1, oacc[ni][3] * inv1);
    }
}

// ---------------------------------------------------------------------------
// Epilogue reductions (norms come from g_sumsq; no normalize pass)
// ---------------------------------------------------------------------------
__device__ __forceinline__ float block_reduce_sum(float v, float* sbuf)
{
    int lane = threadIdx.x & 31, w = threadIdx.x >> 5;
    #pragma unroll
    for (int o = 16; o; o >>= 1) v += __shfl_xor_sync(0xffffffffu, v, o);
    if (lane == 0) sbuf[w] = v;
    __syncthreads();
    float s = (threadIdx.x < (blockDim.x >> 5)) ? sbuf[threadIdx.x] : 0.f;
    if (w == 0) {
        #pragma unroll
        for (int o = 4; o; o >>= 1) s += __shfl_xor_sync(0xffffffffu, s, o);
        if (lane == 0) sbuf[0] = s;
    }
    __syncthreads();
    return sbuf[0];
}

__global__ __launch_bounds__(256) void mean_kernel()
{
    __shared__ float sinv[B_];
    int t = blockIdx.y;
    int d = blockIdx.x * 256 + threadIdx.x;
    for (int i = threadIdx.x; i < B_; i += 256) {
        float ss = g_sumsq[t * B_ + i];
        sinv[i] = 1.f / fmaxf(sqrtf(ss), 1e-8f);
    }
    __syncthreads();
    const float* base = g_out + (size_t)t * B_ * D_ + d;
    float s = 0.f;
    for (int b = 0; b < B_; ++b) s += base[(size_t)b * D_] * sinv[b];
    g_mean[t * D_ + d] = s * (1.f / B_);
}

__global__ __launch_bounds__(256) void adj_kernel(float* __restrict__ outp)
{
    __shared__ float sbuf[32];
    int row = blockIdx.x;
    int t = row / B_;
    const float* x = g_out + (size_t)row * D_;
    const float* m = g_mean + t * D_;
    float s = 0.f;
    for (int i = threadIdx.x; i < D_; i += 256) s += x[i] * m[i];
    s = block_reduce_sum(s, sbuf);
    if (threadIdx.x == 0) {
        float inv = 1.f / fmaxf(sqrtf(g_sumsq[row]), 1e-8f);
        outp[row] = s * inv;
    }
}

// ---------------------------------------------------------------------------

extern "C" void kernel_launch(void* const* d_in, const int* in_sizes, int n_in,
                              void* d_out, int out_size)
{
    const float* node = (const float*)d_in[0];
    const float* w1   = (const float*)d_in[1];
    const float* b1   = (const float*)d_in[2];
    const float* w2   = (const float*)d_in[3];
    const float* b2   = (const float*)d_in[4];
    float* outp = (float*)d_out;

    float* outb;
    cudaGetSymbolAddress((void**)&outb, g_out);
    __half *qkv, *nodeh, *ctxh, *w1h, *w2h;
    cudaGetSymbolAddress((void**)&qkv,   g_qkv);
    cudaGetSymbolAddress((void**)&nodeh, g_node);
    cudaGetSymbolAddress((void**)&ctxh,  g_ctx);
    cudaGetSymbolAddress((void**)&w1h,   g_w1);
    cudaGetSymbolAddress((void**)&w2h,   g_w2);

    const int gemm_smem = 3 * SOFF;        // 110592 B
    cudaFuncSetAttribute(gemm_mma, cudaFuncAttributeMaxDynamicSharedMemorySize, gemm_smem);
    cudaFuncSetAttribute(attn_mma_kernel, cudaFuncAttributeMaxDynamicSharedMemorySize, ATTN_SMEM);

    // convert inputs to fp16; zero sumsq accumulator
    {
        int n4 = NROWS * D_ / 4;
        cvt_kernel<<<(n4 + 255)/256, 256>>>((const float4*)node, (__half2*)nodeh, n4);
        int w14 = E3_ * D_ / 4;
        cvt_kernel<<<(w14 + 255)/256, 256>>>((const float4*)w1, (__half2*)w1h, w14);
        int w24 = D_ * D_ / 4;
        cvt_kernel<<<(w24 + 255)/256, 256>>>((const float4*)w2, (__half2*)w2h, w24);
        zero_kernel<<<NROWS/256, 256>>>();
    }

    // 1. QKV projection -> fp16 qkv (q cols pre-scaled by 0.125)
    gemm_mma<<<dim3(E3_/128, NROWS/128), 256, gemm_smem>>>(
        nodeh, w1h, b1, nullptr, qkv, E3_, 1, D_);

    // 2. Tensor-core flash attention -> ctx fp16
    attn_mma_kernel<<<dim3(B_/128, H_, T_), 256, ATTN_SMEM>>>();

    // 3. Out projection -> fp32 g_out + fused per-row sumsq
    gemm_mma<<<dim3(D_/128, NROWS/128), 256, gemm_smem>>>(
        ctxh, w2h, b2, outb, nullptr, D_, 0, 0);

    // 4. Epilogue: mean of normalized rows, then adj = inv * (out . mean)
    mean_kernel<<<dim3(D_/256, T_), 256>>>();
    adj_kernel<<<NROWS, 256>>>(outp);
}